// round 14
// baseline (speedup 1.0000x reference)
#include <cuda_runtime.h>
#include <cstdint>

#define B_SZ  32
#define T_LEN 2048
#define I_DIM 128
#define H_DIM 256

// Scratch (allocation-free rule: __device__ globals)
__device__ __align__(256) float g_xB[B_SZ * T_LEN * H_DIM];  // 67 MB
__device__ __align__(256) float g_hs[B_SZ * T_LEN * H_DIM];  // 67 MB

// ---------------------------------------------------------------------------
// helpers
// ---------------------------------------------------------------------------
__device__ __forceinline__ uint32_t smem_u32(const void* p) {
    uint32_t a;
    asm("{ .reg .u64 t; cvta.to.shared.u64 t, %1; cvt.u32.u64 %0, t; }"
        : "=r"(a) : "l"(p));
    return a;
}

// packed fp32x2 FMA: full-rate FMA path on sm_103a (3-reg FFMA is half rate)
__device__ __forceinline__ void ffma2(unsigned long long& acc,
                                      unsigned long long a,
                                      unsigned long long b) {
    asm("fma.rn.f32x2 %0, %1, %2, %0;" : "+l"(acc) : "l"(a), "l"(b));
}
__device__ __forceinline__ unsigned long long pack2(float lo, float hi) {
    unsigned long long r;
    asm("mov.b64 %0, {%1, %2};" : "=l"(r) : "f"(lo), "f"(hi));
    return r;
}
__device__ __forceinline__ float2 unpack2(unsigned long long v) {
    float2 r;
    asm("mov.b64 {%0, %1}, %2;" : "=f"(r.x), "=f"(r.y) : "l"(v));
    return r;
}

// tanh(x) = 1 - 2/(exp(2x)+1), via MUFU.EX2 + MUFU.RCP. Abs err ~1e-7.
__device__ __forceinline__ float fast_tanh(float x) {
    float e, r;
    float t = x * 2.8853900817779268f;      // 2*log2(e)
    asm("ex2.approx.f32 %0, %1;" : "=f"(e) : "f"(t));
    float d = e + 1.0f;
    asm("rcp.approx.f32 %0, %1;" : "=f"(r) : "f"(d));
    return fmaf(-2.0f, r, 1.0f);
}

// ---------------------------------------------------------------------------
// Scan kernel: cluster of 2 CTAs per batch element.
//   CTA rank r owns output columns j in [128r, 128r+128).
//   256 threads: jj = tid&127 (output col), q = tid>>7.
//   q0 threads (warps 0-3) consume the LOCALLY produced h half,
//   q1 threads (warps 4-7) consume the PEER half.
//
//   R14 exchange — NO mbarriers, NO async proxy, NO try_wait:
//     producer (q0): plain st.shared::cluster of the 128 h values into the
//       peer's h buffer, then per-warp: __syncwarp (intra-warp HB over the
//       32 data stores) + fence.acq_rel.cluster + ONE relaxed remote store
//       of a monotone counter flag (value t+1) into the peer's flags[w].
//     consumer (q1): spins on its LOCAL flags[0..3] with ld.acquire.cluster
//       (cheap broadcast LDS, ~30cyc/poll) until all >= t.
//   Monotone counters eliminate parity bookkeeping. Double-buffered h plus
//   the mutual t/t+1 lockstep of the recurrence bounds producer/consumer
//   skew to one step: the peer can only clobber buf[t&1] (with h_{t+2})
//   after seeing MY flag t+1, which I send only after my q1 finished
//   reading h_t (bar #1 precedes the send).
// ---------------------------------------------------------------------------
__global__ void __cluster_dims__(2, 1, 1) __launch_bounds__(256, 1)
scan_kernel(const float* __restrict__ A)
{
    __shared__ __align__(16) float h_s[2][H_DIM];   // double-buffered state
    __shared__ float scratch[128];                  // pair-reduce partials
    __shared__ __align__(16) uint32_t flags[4];     // peer-written counters

    const int tid   = threadIdx.x;
    const int jj    = tid & 127;
    const int q     = tid >> 7;            // 0 or 1  (warp-uniform)
    uint32_t rank;
    asm("mov.u32 %0, %%cluster_ctarank;" : "=r"(rank));
    const int b     = blockIdx.x >> 1;
    const int j     = (int)rank * 128 + jj;            // global output column
    // q0 -> local half (rank*128), q1 -> peer half
    const int kbase = (int)(((q + rank) & 1u) * 128);

    // --- A slice -> registers, packed as (A[k][j], A[k+1][j]) pairs --------
    unsigned long long Ar[64];
#pragma unroll
    for (int m = 0; m < 64; m++) {
        float a0 = A[(size_t)(kbase + 2 * m)     * H_DIM + j];
        float a1 = A[(size_t)(kbase + 2 * m + 1) * H_DIM + j];
        Ar[m] = pack2(a0, a1);
    }

    // --- init shared state + flags ------------------------------------------
    h_s[0][tid] = 0.0f;          // tid covers 0..255 == H_DIM
    h_s[1][tid] = 0.0f;
    if (tid < 4) flags[tid] = 0u;

    // cluster-wide visibility of init/zeros before any remote traffic
    asm volatile("barrier.cluster.arrive.aligned;" ::: "memory");
    asm volatile("barrier.cluster.wait.aligned;"   ::: "memory");

    // --- peer addresses (DSMEM, generic proxy) ------------------------------
    uint32_t peer = rank ^ 1u;
    uint32_t h0_a    = smem_u32(&h_s[0][0]);
    uint32_t flags_a = smem_u32(&flags[0]);
    uint32_t peer_h0, peer_flags;
    asm("mapa.shared::cluster.u32 %0, %1, %2;" : "=r"(peer_h0)    : "r"(h0_a),    "r"(peer));
    asm("mapa.shared::cluster.u32 %0, %1, %2;" : "=r"(peer_flags) : "r"(flags_a), "r"(peer));

    // --- xB prefetch pipeline (distance 2 hides DRAM latency) ---------------
    const float* xb_base = g_xB + ((size_t)b * T_LEN) * H_DIM + j;
    float*       hs_out  = g_hs + ((size_t)b * T_LEN) * H_DIM + j;
    float xb_pre[2] = {0.0f, 0.0f};
    if (q == 0) {
        xb_pre[0] = __ldg(xb_base);
        xb_pre[1] = __ldg(xb_base + H_DIM);
    }

    const int lane0 = ((tid & 31) == 0);
    const int w     = (tid >> 5) & 3;       // producer warp index within q0

    // --- main scan loop -----------------------------------------------------
    for (int t = 0; t < T_LEN; t++) {
        const int cur = t & 1;
        const int nxt = cur ^ 1;

        // q1: spin on LOCAL flags until the peer's step-(t-1) push (flag
        // value >= t) has fully landed. t=0 passes immediately (flags=0).
        if (q == 1) {
            for (;;) {
                uint32_t f0, f1, f2, f3;
                asm volatile("ld.acquire.cluster.shared::cta.u32 %0, [%1];"
                             : "=r"(f0) : "r"(flags_a)       : "memory");
                asm volatile("ld.acquire.cluster.shared::cta.u32 %0, [%1];"
                             : "=r"(f1) : "r"(flags_a + 4u)  : "memory");
                asm volatile("ld.acquire.cluster.shared::cta.u32 %0, [%1];"
                             : "=r"(f2) : "r"(flags_a + 8u)  : "memory");
                asm volatile("ld.acquire.cluster.shared::cta.u32 %0, [%1];"
                             : "=r"(f3) : "r"(flags_a + 12u) : "memory");
                if ((int)f0 >= t && (int)f1 >= t &&
                    (int)f2 >= t && (int)f3 >= t) break;
            }
        }

        // dot over my 128 k values (4 accumulators: chain 64 cyc, not 128)
        const ulonglong2* h2 =
            reinterpret_cast<const ulonglong2*>(&h_s[cur][kbase]);
        unsigned long long acc0 = 0ull, acc1 = 0ull, acc2 = 0ull, acc3 = 0ull;
#pragma unroll
        for (int m = 0; m < 16; m++) {
            ulonglong2 hv0 = h2[2 * m];
            ulonglong2 hv1 = h2[2 * m + 1];
            ffma2(acc0, hv0.x, Ar[4 * m]);
            ffma2(acc1, hv0.y, Ar[4 * m + 1]);
            ffma2(acc2, hv1.x, Ar[4 * m + 2]);
            ffma2(acc3, hv1.y, Ar[4 * m + 3]);
        }
        float2 u0 = unpack2(acc0), u1 = unpack2(acc1);
        float2 u2 = unpack2(acc2), u3 = unpack2(acc3);
        float partial = ((u0.x + u0.y) + (u1.x + u1.y)) +
                        ((u2.x + u2.y) + (u3.x + u3.y));

        if (q == 1) scratch[jj] = partial;
        __syncthreads();    // bar #1: scratch ready; q1 done reading h_s[cur]

        if (q == 0) {
            float tot = partial + scratch[jj] + xb_pre[t & 1];
            if (t + 2 < T_LEN)   // refill prefetch slot
                xb_pre[t & 1] = __ldg(xb_base + (size_t)(t + 2) * H_DIM);
            float hv = fast_tanh(tot);

            h_s[nxt][j] = hv;                   // local copy (my half)
            hs_out[(size_t)t * H_DIM] = hv;     // for out-GEMM

            if (t + 1 < T_LEN) {
                // push my h value into the peer's h_s[nxt] (generic proxy)
                uint32_t ra = peer_h0 + (uint32_t)((nxt * H_DIM + j) * 4);
                asm volatile("st.shared::cluster.f32 [%0], %1;"
                             :: "r"(ra), "f"(hv) : "memory");
                // per-warp publish: order my warp's 32 data stores before
                // ONE relaxed counter-flag store into the peer's flags[w]
                __syncwarp();
                if (lane0) {
                    asm volatile("fence.acq_rel.cluster;" ::: "memory");
                    asm volatile(
                        "st.relaxed.cluster.shared::cluster.u32 [%0], %1;"
                        :: "r"(peer_flags + (uint32_t)w * 4u),
                           "r"((uint32_t)(t + 1))
                        : "memory");
                }
            }
        }
        __syncthreads();    // bar #2: local h_s[nxt] half visible CTA-wide;
                            // also fences scratch reuse across iterations
    }

    // no CTA may exit while the peer might still remote-store into it
    asm volatile("barrier.cluster.arrive.aligned;" ::: "memory");
    asm volatile("barrier.cluster.wait.aligned;"   ::: "memory");
}

// ---------------------------------------------------------------------------
// fp32 tiled GEMM: C[M,N] = A[M,K] @ B[K,N], all row-major.
// 128x128 block tile, k-tile 16, 256 threads, 8x8 microtile, FFMA2 accums.
// (~90% of fp32 FMA roofline measured; unchanged.)
// ---------------------------------------------------------------------------
__global__ void __launch_bounds__(256)
gemm_f32(const float* __restrict__ Ag, const float* __restrict__ Bg,
         float* __restrict__ Cg, int M, int N, int K)
{
    __shared__ __align__(16) float As[16][128];   // transposed A tile
    __shared__ __align__(16) float Bs[16][128];

    const int tid = threadIdx.x;
    const int bm  = blockIdx.x * 128;
    const int bn  = blockIdx.y * 128;
    const int tx  = tid & 15;     // n direction
    const int ty  = tid >> 4;     // m direction
    const int m0  = ty * 8;
    const int n0  = tx * 8;

    unsigned long long acc[8][4];
#pragma unroll
    for (int i = 0; i < 8; i++)
#pragma unroll
        for (int p = 0; p < 4; p++) acc[i][p] = 0ull;

    for (int k0 = 0; k0 < K; k0 += 16) {
#pragma unroll
        for (int l = 0; l < 2; l++) {
            int v  = tid + l * 256;
            int r  = v >> 2;
            int c4 = v & 3;
            float4 a = *reinterpret_cast<const float4*>(
                &Ag[(size_t)(bm + r) * K + k0 + c4 * 4]);
            As[c4 * 4 + 0][r] = a.x;
            As[c4 * 4 + 1][r] = a.y;
            As[c4 * 4 + 2][r] = a.z;
            As[c4 * 4 + 3][r] = a.w;
        }
#pragma unroll
        for (int l = 0; l < 2; l++) {
            int v  = tid + l * 256;
            int kk = v >> 5;
            int c4 = v & 31;
            *reinterpret_cast<float4*>(&Bs[kk][c4 * 4]) =
                *reinterpret_cast<const float4*>(
                    &Bg[(size_t)(k0 + kk) * N + bn + c4 * 4]);
        }
        __syncthreads();

#pragma unroll
        for (int kk = 0; kk < 16; kk++) {
            float4 a0 = *reinterpret_cast<const float4*>(&As[kk][m0]);
            float4 a1 = *reinterpret_cast<const float4*>(&As[kk][m0 + 4]);
            ulonglong2 b0 = *reinterpret_cast<const ulonglong2*>(&Bs[kk][n0]);
            ulonglong2 b1 = *reinterpret_cast<const ulonglong2*>(&Bs[kk][n0 + 4]);

            unsigned long long ap[8];
            ap[0] = pack2(a0.x, a0.x); ap[1] = pack2(a0.y, a0.y);
            ap[2] = pack2(a0.z, a0.z); ap[3] = pack2(a0.w, a0.w);
            ap[4] = pack2(a1.x, a1.x); ap[5] = pack2(a1.y, a1.y);
            ap[6] = pack2(a1.z, a1.z); ap[7] = pack2(a1.w, a1.w);
            unsigned long long bv0 = b0.x, bv1 = b0.y, bv2 = b1.x, bv3 = b1.y;

#pragma unroll
            for (int i = 0; i < 8; i++) {
                ffma2(acc[i][0], ap[i], bv0);
                ffma2(acc[i][1], ap[i], bv1);
                ffma2(acc[i][2], ap[i], bv2);
                ffma2(acc[i][3], ap[i], bv3);
            }
        }
        __syncthreads();
    }

#pragma unroll
    for (int i = 0; i < 8; i++) {
        float o[8];
#pragma unroll
        for (int p = 0; p < 4; p++) {
            float2 u = unpack2(acc[i][p]);
            o[2 * p] = u.x; o[2 * p + 1] = u.y;
        }
        float4* dst = reinterpret_cast<float4*>(
            &Cg[(size_t)(bm + m0 + i) * N + bn + n0]);
        dst[0] = make_float4(o[0], o[1], o[2], o[3]);
        dst[1] = make_float4(o[4], o[5], o[6], o[7]);
    }
}

// ---------------------------------------------------------------------------
// launch
// ---------------------------------------------------------------------------
extern "C" void kernel_launch(void* const* d_in, const int* in_sizes, int n_in,
                              void* d_out, int out_size)
{
    (void)in_sizes; (void)n_in; (void)out_size;
    const float* x  = (const float*)d_in[0];   // [32, 2048, 128]
    const float* A  = (const float*)d_in[1];   // [256, 256]
    const float* Bm = (const float*)d_in[2];   // [128, 256]
    const float* C  = (const float*)d_in[3];   // [256, 256]
    float* out = (float*)d_out;                // [32, 2048, 256]

    float* xB = nullptr;
    float* hs = nullptr;
    cudaGetSymbolAddress((void**)&xB, g_xB);   // pure query: capture-safe
    cudaGetSymbolAddress((void**)&hs, g_hs);

    const int M = B_SZ * T_LEN;                // 65536

    // 1) xB = x @ Bm   (M x 128) @ (128 x 256)
    gemm_f32<<<dim3(M / 128, H_DIM / 128), 256>>>(x, Bm, xB, M, H_DIM, I_DIM);
    // 2) sequential tanh scan, 32 clusters of 2 CTAs
    scan_kernel<<<B_SZ * 2, 256>>>(A);
    // 3) out = hs @ C  (M x 256) @ (256 x 256)
    gemm_f32<<<dim3(M / 128, H_DIM / 128), 256>>>(hs, C, out, M, H_DIM, H_DIM);
}

// round 15
// speedup vs baseline: 1.2088x; 1.2088x over previous
#include <cuda_runtime.h>
#include <cstdint>

#define B_SZ  32
#define T_LEN 2048
#define I_DIM 128
#define H_DIM 256

// Scratch (allocation-free rule: __device__ globals)
__device__ __align__(256) float g_xB[B_SZ * T_LEN * H_DIM];  // 67 MB
__device__ __align__(256) float g_hs[B_SZ * T_LEN * H_DIM];  // 67 MB

// ---------------------------------------------------------------------------
// helpers
// ---------------------------------------------------------------------------
__device__ __forceinline__ uint32_t smem_u32(const void* p) {
    uint32_t a;
    asm("{ .reg .u64 t; cvta.to.shared.u64 t, %1; cvt.u32.u64 %0, t; }"
        : "=r"(a) : "l"(p));
    return a;
}

// packed fp32x2 FMA: full-rate FMA path on sm_103a (3-reg FFMA is half rate)
__device__ __forceinline__ void ffma2(unsigned long long& acc,
                                      unsigned long long a,
                                      unsigned long long b) {
    asm("fma.rn.f32x2 %0, %1, %2, %0;" : "+l"(acc) : "l"(a), "l"(b));
}
__device__ __forceinline__ unsigned long long pack2(float lo, float hi) {
    unsigned long long r;
    asm("mov.b64 %0, {%1, %2};" : "=l"(r) : "f"(lo), "f"(hi));
    return r;
}
__device__ __forceinline__ unsigned long long pack2u(uint32_t lo, uint32_t hi) {
    unsigned long long r;
    asm("mov.b64 %0, {%1, %2};" : "=l"(r) : "r"(lo), "r"(hi));
    return r;
}
__device__ __forceinline__ float2 unpack2(unsigned long long v) {
    float2 r;
    asm("mov.b64 {%0, %1}, %2;" : "=f"(r.x), "=f"(r.y) : "l"(v));
    return r;
}

// tanh(x) = 1 - 2/(exp(2x)+1), via MUFU.EX2 + MUFU.RCP. Abs err ~1e-7.
__device__ __forceinline__ float fast_tanh(float x) {
    float e, r;
    float t = x * 2.8853900817779268f;      // 2*log2(e)
    asm("ex2.approx.f32 %0, %1;" : "=f"(e) : "f"(t));
    float d = e + 1.0f;
    asm("rcp.approx.f32 %0, %1;" : "=f"(r) : "f"(d));
    return fmaf(-2.0f, r, 1.0f);
}

// ---------------------------------------------------------------------------
// Scan kernel: cluster of 2 CTAs per batch element.
//   CTA rank r owns output columns j in [128r, 128r+128).
//   256 threads: jj = tid&127 (output col), q = tid>>7.
//   q0 warps consume the LOCALLY produced h half; q1 warps consume the
//   PEER half -> only q1 ever blocks.
//
//   R15 exchange — TAG-IN-DATA, zero ordering primitives:
//     Every h value travels as ONE aligned 8-byte word {f32 h, u32 tag}
//     (tag = step index of the state). An aligned 64-bit store is atomic,
//     so tag-visible <=> value-visible BY CONSTRUCTION: no fences, no
//     mbarriers, no release/acquire, no async proxy anywhere in the loop.
//     q0 lanes: one st.shared::cluster.b64 each into the peer's tagged
//     buffer (+ the same word into the local tagged buffer).
//     q1 lanes: each polls ITS OWN word with plain volatile LDS (~29cyc)
//     until tag >= t, then bar.sync 1,128 across the q1 warps proves all
//     128 words landed; smem is physically shared, so every landed word
//     is visible to every thread.
//   Clobber safety (double buffer by parity): the peer can only overwrite
//   buffer t&1 (with state t+2) after consuming MY state t+1, which I send
//   only after bar#1 of step t — by which point my readers of buffer t&1
//   finished one full step earlier.
// ---------------------------------------------------------------------------
__global__ void __cluster_dims__(2, 1, 1) __launch_bounds__(256, 1)
scan_kernel(const float* __restrict__ A)
{
    // tagged state: [parity][global column] = {h bits, tag}
    __shared__ __align__(16) uint2 h_tag[2][H_DIM];
    __shared__ float scratch[128];                  // pair-reduce partials

    const int tid   = threadIdx.x;
    const int jj    = tid & 127;
    const int q     = tid >> 7;            // 0 or 1  (warp-uniform)
    uint32_t rank;
    asm("mov.u32 %0, %%cluster_ctarank;" : "=r"(rank));
    const int b     = blockIdx.x >> 1;
    const int j     = (int)rank * 128 + jj;            // global output column
    // q0 -> local half (rank*128), q1 -> peer half
    const int kbase = (int)(((q + rank) & 1u) * 128);

    // --- A slice -> registers, packed as (A[k][j], A[k+1][j]) pairs --------
    unsigned long long Ar[64];
#pragma unroll
    for (int m = 0; m < 64; m++) {
        float a0 = A[(size_t)(kbase + 2 * m)     * H_DIM + j];
        float a1 = A[(size_t)(kbase + 2 * m + 1) * H_DIM + j];
        Ar[m] = pack2(a0, a1);
    }

    // --- init tagged state: h=0, tag=0 (step-0 poll `tag>=0` passes) -------
    h_tag[0][tid] = make_uint2(0u, 0u);    // tid covers 0..255 == H_DIM
    h_tag[1][tid] = make_uint2(0u, 0u);

    // cluster-wide visibility of the zero-init before any remote traffic
    asm volatile("barrier.cluster.arrive.aligned;" ::: "memory");
    asm volatile("barrier.cluster.wait.aligned;"   ::: "memory");

    // --- peer addresses (DSMEM, generic proxy) ------------------------------
    uint32_t peer = rank ^ 1u;
    uint32_t htag_a = smem_u32(&h_tag[0][0]);
    uint32_t peer_htag;
    asm("mapa.shared::cluster.u32 %0, %1, %2;"
        : "=r"(peer_htag) : "r"(htag_a), "r"(peer));

    // --- xB prefetch pipeline (distance 2 hides DRAM latency) ---------------
    const float* xb_base = g_xB + ((size_t)b * T_LEN) * H_DIM + j;
    float*       hs_out  = g_hs + ((size_t)b * T_LEN) * H_DIM + j;
    float xb_pre[2] = {0.0f, 0.0f};
    if (q == 0) {
        xb_pre[0] = __ldg(xb_base);
        xb_pre[1] = __ldg(xb_base + H_DIM);
    }

    // address of the one word THIS q1 thread polls (its k = kbase + jj)
    const uint32_t my_poll_base = htag_a + (uint32_t)((kbase + jj) * 8);

    // --- main scan loop -----------------------------------------------------
    for (int t = 0; t < T_LEN; t++) {
        const int cur = t & 1;
        const int nxt = cur ^ 1;

        // q1: poll OWN word in the current parity buffer until the peer's
        // step-t state has landed (tag monotone, 64-bit word atomic).
        if (q == 1) {
            uint32_t addr = my_poll_base + (uint32_t)(cur * H_DIM * 8);
            uint32_t hv_, tg_;
            do {
                asm volatile("ld.volatile.shared.v2.u32 {%0, %1}, [%2];"
                             : "=r"(hv_), "=r"(tg_) : "r"(addr) : "memory");
            } while (tg_ < (uint32_t)t);
            // all 128 q1 threads verified their word -> whole half landed
            asm volatile("bar.sync 1, 128;" ::: "memory");
        }

        // dot over my 128 k values from the tagged array:
        // uint4 = {h_k, tag, h_k+1, tag} -> pack h_k,h_k+1 -> one ffma2.
        const uint4* hp =
            reinterpret_cast<const uint4*>(&h_tag[cur][kbase]);
        unsigned long long acc0 = 0ull, acc1 = 0ull, acc2 = 0ull, acc3 = 0ull;
#pragma unroll
        for (int m = 0; m < 64; m += 4) {
            uint4 w0 = hp[m + 0];
            uint4 w1 = hp[m + 1];
            uint4 w2 = hp[m + 2];
            uint4 w3 = hp[m + 3];
            ffma2(acc0, pack2u(w0.x, w0.z), Ar[m + 0]);
            ffma2(acc1, pack2u(w1.x, w1.z), Ar[m + 1]);
            ffma2(acc2, pack2u(w2.x, w2.z), Ar[m + 2]);
            ffma2(acc3, pack2u(w3.x, w3.z), Ar[m + 3]);
        }
        float2 u0 = unpack2(acc0), u1 = unpack2(acc1);
        float2 u2 = unpack2(acc2), u3 = unpack2(acc3);
        float partial = ((u0.x + u0.y) + (u1.x + u1.y)) +
                        ((u2.x + u2.y) + (u3.x + u3.y));

        if (q == 1) scratch[jj] = partial;
        __syncthreads();    // bar #1: scratch ready; q1 done with buf[cur]

        if (q == 0) {
            float tot = partial + scratch[jj] + xb_pre[t & 1];
            if (t + 2 < T_LEN)   // refill prefetch slot
                xb_pre[t & 1] = __ldg(xb_base + (size_t)(t + 2) * H_DIM);
            float hv = fast_tanh(tot);

            // one atomic 8B word: {h bits, tag = t+1}
            unsigned long long payload =
                pack2u(__float_as_uint(hv), (uint32_t)(t + 1));
            uint32_t off = (uint32_t)((nxt * H_DIM + j) * 8);

            if (t + 1 < T_LEN) {
                // remote first: start the DSMEM flight ASAP (critical path)
                asm volatile("st.shared::cluster.b64 [%0], %1;"
                             :: "r"(peer_htag + off), "l"(payload) : "memory");
            }
            // local copy (my half), same tagged format
            asm volatile("st.shared.b64 [%0], %1;"
                         :: "r"(htag_a + off), "l"(payload) : "memory");

            hs_out[(size_t)t * H_DIM] = hv;     // for out-GEMM
        }
        __syncthreads();    // bar #2: local half of buf[nxt] visible CTA-wide
    }

    // no CTA may exit while the peer might still remote-store into it
    asm volatile("barrier.cluster.arrive.aligned;" ::: "memory");
    asm volatile("barrier.cluster.wait.aligned;"   ::: "memory");
}

// ---------------------------------------------------------------------------
// fp32 tiled GEMM: C[M,N] = A[M,K] @ B[K,N], all row-major.
// 128x128 block tile, k-tile 16, 256 threads, 8x8 microtile, FFMA2 accums.
// (~90% of fp32 FMA roofline measured; unchanged.)
// ---------------------------------------------------------------------------
__global__ void __launch_bounds__(256)
gemm_f32(const float* __restrict__ Ag, const float* __restrict__ Bg,
         float* __restrict__ Cg, int M, int N, int K)
{
    __shared__ __align__(16) float As[16][128];   // transposed A tile
    __shared__ __align__(16) float Bs[16][128];

    const int tid = threadIdx.x;
    const int bm  = blockIdx.x * 128;
    const int bn  = blockIdx.y * 128;
    const int tx  = tid & 15;     // n direction
    const int ty  = tid >> 4;     // m direction
    const int m0  = ty * 8;
    const int n0  = tx * 8;

    unsigned long long acc[8][4];
#pragma unroll
    for (int i = 0; i < 8; i++)
#pragma unroll
        for (int p = 0; p < 4; p++) acc[i][p] = 0ull;

    for (int k0 = 0; k0 < K; k0 += 16) {
#pragma unroll
        for (int l = 0; l < 2; l++) {
            int v  = tid + l * 256;
            int r  = v >> 2;
            int c4 = v & 3;
            float4 a = *reinterpret_cast<const float4*>(
                &Ag[(size_t)(bm + r) * K + k0 + c4 * 4]);
            As[c4 * 4 + 0][r] = a.x;
            As[c4 * 4 + 1][r] = a.y;
            As[c4 * 4 + 2][r] = a.z;
            As[c4 * 4 + 3][r] = a.w;
        }
#pragma unroll
        for (int l = 0; l < 2; l++) {
            int v  = tid + l * 256;
            int kk = v >> 5;
            int c4 = v & 31;
            *reinterpret_cast<float4*>(&Bs[kk][c4 * 4]) =
                *reinterpret_cast<const float4*>(
                    &Bg[(size_t)(k0 + kk) * N + bn + c4 * 4]);
        }
        __syncthreads();

#pragma unroll
        for (int kk = 0; kk < 16; kk++) {
            float4 a0 = *reinterpret_cast<const float4*>(&As[kk][m0]);
            float4 a1 = *reinterpret_cast<const float4*>(&As[kk][m0 + 4]);
            ulonglong2 b0 = *reinterpret_cast<const ulonglong2*>(&Bs[kk][n0]);
            ulonglong2 b1 = *reinterpret_cast<const ulonglong2*>(&Bs[kk][n0 + 4]);

            unsigned long long ap[8];
            ap[0] = pack2(a0.x, a0.x); ap[1] = pack2(a0.y, a0.y);
            ap[2] = pack2(a0.z, a0.z); ap[3] = pack2(a0.w, a0.w);
            ap[4] = pack2(a1.x, a1.x); ap[5] = pack2(a1.y, a1.y);
            ap[6] = pack2(a1.z, a1.z); ap[7] = pack2(a1.w, a1.w);
            unsigned long long bv0 = b0.x, bv1 = b0.y, bv2 = b1.x, bv3 = b1.y;

#pragma unroll
            for (int i = 0; i < 8; i++) {
                ffma2(acc[i][0], ap[i], bv0);
                ffma2(acc[i][1], ap[i], bv1);
                ffma2(acc[i][2], ap[i], bv2);
                ffma2(acc[i][3], ap[i], bv3);
            }
        }
        __syncthreads();
    }

#pragma unroll
    for (int i = 0; i < 8; i++) {
        float o[8];
#pragma unroll
        for (int p = 0; p < 4; p++) {
            float2 u = unpack2(acc[i][p]);
            o[2 * p] = u.x; o[2 * p + 1] = u.y;
        }
        float4* dst = reinterpret_cast<float4*>(
            &Cg[(size_t)(bm + m0 + i) * N + bn + n0]);
        dst[0] = make_float4(o[0], o[1], o[2], o[3]);
        dst[1] = make_float4(o[4], o[5], o[6], o[7]);
    }
}

// ---------------------------------------------------------------------------
// launch
// ---------------------------------------------------------------------------
extern "C" void kernel_launch(void* const* d_in, const int* in_sizes, int n_in,
                              void* d_out, int out_size)
{
    (void)in_sizes; (void)n_in; (void)out_size;
    const float* x  = (const float*)d_in[0];   // [32, 2048, 128]
    const float* A  = (const float*)d_in[1];   // [256, 256]
    const float* Bm = (const float*)d_in[2];   // [128, 256]
    const float* C  = (const float*)d_in[3];   // [256, 256]
    float* out = (float*)d_out;                // [32, 2048, 256]

    float* xB = nullptr;
    float* hs = nullptr;
    cudaGetSymbolAddress((void**)&xB, g_xB);   // pure query: capture-safe
    cudaGetSymbolAddress((void**)&hs, g_hs);

    const int M = B_SZ * T_LEN;                // 65536

    // 1) xB = x @ Bm   (M x 128) @ (128 x 256)
    gemm_f32<<<dim3(M / 128, H_DIM / 128), 256>>>(x, Bm, xB, M, H_DIM, I_DIM);
    // 2) sequential tanh scan, 32 clusters of 2 CTAs
    scan_kernel<<<B_SZ * 2, 256>>>(A);
    // 3) out = hs @ C  (M x 256) @ (256 x 256)
    gemm_f32<<<dim3(M / 128, H_DIM / 128), 256>>>(hs, C, out, M, H_DIM, H_DIM);
}